// round 1
// baseline (speedup 1.0000x reference)
#include <cuda_runtime.h>
#include <cstdint>

// Circular convolution of 8192 rows of length 4096 via packed-real FFT.
// One CTA per row, 512 threads, radix-8 Stockham (4 stages), ping-pong smem.

#define NFFT 4096
#define NTHREADS 512

__device__ __forceinline__ int pad(int i) { return i + (i >> 3); }

__device__ __forceinline__ float2 cadd(float2 a, float2 b) { return make_float2(a.x + b.x, a.y + b.y); }
__device__ __forceinline__ float2 csub(float2 a, float2 b) { return make_float2(a.x - b.x, a.y - b.y); }
__device__ __forceinline__ float2 cmul(float2 a, float2 b) {
    return make_float2(fmaf(a.x, b.x, -a.y * b.y), fmaf(a.x, b.y, a.y * b.x));
}

// Multiply by i*S (S = -1 forward, +1 inverse)
template <int S>
__device__ __forceinline__ float2 mul_iS(float2 a) {
    return make_float2(-(float)S * a.y, (float)S * a.x);
}

// 8-point DFT, X_r = sum_j x_j * exp(S*2*pi*i*j*r/8). In-place on v[8].
template <int S>
__device__ __forceinline__ void dft8(float2 v[8]) {
    const float r2 = 0.70710678118654752440f;
    float2 u0 = cadd(v[0], v[4]), d0 = csub(v[0], v[4]);
    float2 u1 = cadd(v[1], v[5]), d1 = csub(v[1], v[5]);
    float2 u2 = cadd(v[2], v[6]), d2 = csub(v[2], v[6]);
    float2 u3 = cadd(v[3], v[7]), d3 = csub(v[3], v[7]);
    // e1 = d1 * W8^1 = d1 * (1 + iS)/sqrt2
    float2 e1 = make_float2((d1.x - (float)S * d1.y) * r2, (d1.y + (float)S * d1.x) * r2);
    // e2 = d2 * W8^2 = d2 * iS
    float2 e2 = mul_iS<S>(d2);
    // e3 = d3 * W8^3 = d3 * (-1 + iS)/sqrt2
    float2 e3 = make_float2((-d3.x - (float)S * d3.y) * r2, (-d3.y + (float)S * d3.x) * r2);

    // DFT4 of (u0,u1,u2,u3) -> X0,X2,X4,X6
    float2 p0 = cadd(u0, u2), p1 = cadd(u1, u3);
    float2 q0 = csub(u0, u2), q1 = mul_iS<S>(csub(u1, u3));
    v[0] = cadd(p0, p1); v[2] = cadd(q0, q1);
    v[4] = csub(p0, p1); v[6] = csub(q0, q1);

    // DFT4 of (d0,e1,e2,e3) -> X1,X3,X5,X7
    float2 P0 = cadd(d0, e2), P1 = cadd(e1, e3);
    float2 Q0 = csub(d0, e2), Q1 = mul_iS<S>(csub(e1, e3));
    v[1] = cadd(P0, P1); v[3] = cadd(Q0, Q1);
    v[5] = csub(P0, P1); v[7] = csub(Q0, Q1);
}

// 4 radix-8 Stockham stages. Data starts in bx, ends in bx (natural order).
// Caller must __syncthreads() after filling bx. Includes trailing __syncthreads().
template <int S>
__device__ __forceinline__ void fft4096(float2* bx, float2* by, int t) {
    float2* src = bx;
    float2* dst = by;
    #pragma unroll
    for (int stage = 0; stage < 4; ++stage) {
        const int ls = 3 * stage;          // log8 shift
        const int s = 1 << ls;             // 1, 8, 64, 512
        const int n = NFFT >> ls;          // 4096, 512, 64, 8
        const int q = t & (s - 1);
        const int p = t >> ls;

        float2 v[8];
        #pragma unroll
        for (int r = 0; r < 8; ++r) v[r] = src[pad(t + NTHREADS * r)];

        dft8<S>(v);

        if (stage < 3) {
            // twiddle W_n^{p*r}, W_n = exp(S*2*pi*i/n); |theta| < 0.79 rad
            float theta = (float)S * 6.283185307179586f * (float)p / (float)n;
            float sn, cs;
            __sincosf(theta, &sn, &cs);
            float2 w1 = make_float2(cs, sn);
            float2 w = w1;
            #pragma unroll
            for (int r = 1; r < 8; ++r) {
                v[r] = cmul(v[r], w);
                w = cmul(w, w1);
            }
        }

        const int base = q + 8 * s * p;
        #pragma unroll
        for (int r = 0; r < 8; ++r) dst[pad(base + s * r)] = v[r];
        __syncthreads();

        float2* tmp = src; src = dst; dst = tmp;
    }
}

extern __shared__ float2 g_smem[];

__global__ void __launch_bounds__(NTHREADS, 2)
circconv_kernel(const float* __restrict__ A, const float* __restrict__ B,
                float* __restrict__ out) {
    float2* bx = g_smem;
    float2* by = g_smem + 4608;  // pad(4095)=4606 -> 4608-slot buffers

    const int row = blockIdx.x;
    const int t = threadIdx.x;
    const float* a = A + (size_t)row * NFFT;
    const float* b = B + (size_t)row * NFFT;

    // Pack z = a + i*b
    #pragma unroll
    for (int r = 0; r < 8; ++r) {
        const int k = t + NTHREADS * r;
        bx[pad(k)] = make_float2(a[k], b[k]);
    }
    __syncthreads();

    // Forward FFT of packed signal (result in bx, natural order)
    fft4096<-1>(bx, by, t);

    // Unpack real spectra A[k], B[k]; pointwise multiply C = A*B into by
    #pragma unroll
    for (int r = 0; r < 8; ++r) {
        const int k = t + NTHREADS * r;
        const int nk = (NFFT - k) & (NFFT - 1);
        const float2 Zk = bx[pad(k)];
        const float2 Zn = bx[pad(nk)];
        // A = (Zk + conj(Zn))/2 ; B = -i*(Zk - conj(Zn))/2
        float2 Ak = make_float2(0.5f * (Zk.x + Zn.x), 0.5f * (Zk.y - Zn.y));
        float2 Bk = make_float2(0.5f * (Zk.y + Zn.y), -0.5f * (Zk.x - Zn.x));
        by[pad(k)] = cmul(Ak, Bk);
    }
    __syncthreads();

    // Inverse FFT (result in by)
    fft4096<1>(by, bx, t);

    float* o = out + (size_t)row * NFFT;
    const float inv = 1.0f / (float)NFFT;
    #pragma unroll
    for (int r = 0; r < 8; ++r) {
        const int k = t + NTHREADS * r;
        o[k] = by[pad(k)].x * inv;
    }
}

extern "C" void kernel_launch(void* const* d_in, const int* in_sizes, int n_in,
                              void* d_out, int out_size) {
    const float* a = (const float*)d_in[0];
    const float* b = (const float*)d_in[1];
    float* out = (float*)d_out;

    const int rows = in_sizes[0] / NFFT;  // 8192
    const size_t smem_bytes = 2 * 4608 * sizeof(float2);  // 73728 B

    cudaFuncSetAttribute(circconv_kernel,
                         cudaFuncAttributeMaxDynamicSharedMemorySize,
                         (int)smem_bytes);
    circconv_kernel<<<rows, NTHREADS, smem_bytes>>>(a, b, out);
}

// round 2
// speedup vs baseline: 1.8533x; 1.8533x over previous
#include <cuda_runtime.h>
#include <cstdint>

// Circular convolution of 8192 rows of length 4096 via packed-real FFT.
// One CTA per row, 256 threads, radix-16 Stockham (3 stages), ping-pong smem.
// Only 5 smem write+read exchanges total (2 fwd, 1 unpack, 2 inv).

#define NFFT 4096
#define NT 256

__device__ __forceinline__ int pad(int i) { return i + (i >> 4); }

__device__ __forceinline__ float2 cadd(float2 a, float2 b) { return make_float2(a.x + b.x, a.y + b.y); }
__device__ __forceinline__ float2 csub(float2 a, float2 b) { return make_float2(a.x - b.x, a.y - b.y); }
__device__ __forceinline__ float2 cmul(float2 a, float2 b) {
    return make_float2(fmaf(a.x, b.x, -a.y * b.y), fmaf(a.x, b.y, a.y * b.x));
}

template <int S>
__device__ __forceinline__ float2 mul_iS(float2 a) {
    return make_float2(-(float)S * a.y, (float)S * a.x);
}

// 8-point DFT, X_r = sum_j x_j * exp(S*2*pi*i*j*r/8). In-place on v[8].
template <int S>
__device__ __forceinline__ void dft8(float2 v[8]) {
    const float r2 = 0.70710678118654752440f;
    float2 u0 = cadd(v[0], v[4]), d0 = csub(v[0], v[4]);
    float2 u1 = cadd(v[1], v[5]), d1 = csub(v[1], v[5]);
    float2 u2 = cadd(v[2], v[6]), d2 = csub(v[2], v[6]);
    float2 u3 = cadd(v[3], v[7]), d3 = csub(v[3], v[7]);
    float2 e1 = make_float2((d1.x - (float)S * d1.y) * r2, (d1.y + (float)S * d1.x) * r2);
    float2 e2 = mul_iS<S>(d2);
    float2 e3 = make_float2((-d3.x - (float)S * d3.y) * r2, (-d3.y + (float)S * d3.x) * r2);

    float2 p0 = cadd(u0, u2), p1 = cadd(u1, u3);
    float2 q0 = csub(u0, u2), q1 = mul_iS<S>(csub(u1, u3));
    v[0] = cadd(p0, p1); v[2] = cadd(q0, q1);
    v[4] = csub(p0, p1); v[6] = csub(q0, q1);

    float2 P0 = cadd(d0, e2), P1 = cadd(e1, e3);
    float2 Q0 = csub(d0, e2), Q1 = mul_iS<S>(csub(e1, e3));
    v[1] = cadd(P0, P1); v[3] = cadd(Q0, Q1);
    v[5] = csub(P0, P1); v[7] = csub(Q0, Q1);
}

// 16-point DFT via even/odd split into two DFT-8s.
template <int S>
__device__ __forceinline__ void dft16(float2 v[16]) {
    float2 e[8], o[8];
    #pragma unroll
    for (int j = 0; j < 8; ++j) { e[j] = v[2 * j]; o[j] = v[2 * j + 1]; }
    dft8<S>(e);
    dft8<S>(o);
    const float COS16[8] = {1.f, 0.9238795325f, 0.7071067812f, 0.3826834324f,
                            0.f, -0.3826834324f, -0.7071067812f, -0.9238795325f};
    const float SIN16[8] = {0.f, 0.3826834324f, 0.7071067812f, 0.9238795325f,
                            1.f, 0.9238795325f, 0.7071067812f, 0.3826834324f};
    #pragma unroll
    for (int k = 0; k < 8; ++k) {
        float2 w = make_float2(COS16[k], (float)S * SIN16[k]);
        float2 t = cmul(o[k], w);
        v[k] = cadd(e[k], t);
        v[k + 8] = csub(e[k], t);
    }
}

// Apply twiddles W_n^{p*r} to v[r], r=0..15, W_n = exp(S*2*pi*i/n).
// Recurrence from w1 with a refresh at r=8 for accuracy.
template <int S>
__device__ __forceinline__ void twiddle16(float2 v[16], int p, float ninv) {
    float th = (float)S * 6.28318530717958647692f * (float)p * ninv;
    float s1, c1; __sincosf(th, &s1, &c1);
    float s8, c8; __sincosf(8.0f * th, &s8, &c8);
    float2 w1 = make_float2(c1, s1);
    float2 w8 = make_float2(c8, s8);
    v[1] = cmul(v[1], w1);
    float2 wr = w1;
    #pragma unroll
    for (int r = 2; r < 8; ++r) { wr = cmul(wr, w1); v[r] = cmul(v[r], wr); }
    v[8] = cmul(v[8], w8);
    wr = w8;
    #pragma unroll
    for (int r = 9; r < 16; ++r) { wr = cmul(wr, w1); v[r] = cmul(v[r], wr); }
}

extern __shared__ float2 g_smem[];

__global__ void __launch_bounds__(NT, 2)
circconv16_kernel(const float* __restrict__ A, const float* __restrict__ B,
                  float* __restrict__ out) {
    float2* bufA = g_smem;
    float2* bufB = g_smem + 4352;  // pad(4095)=4350 -> 4352-slot buffers

    const int row = blockIdx.x;
    const int t = threadIdx.x;
    const float* a = A + (size_t)row * NFFT;
    const float* b = B + (size_t)row * NFFT;

    float2 v[16];

    // Pack z = a + i*b directly into registers (stage-0 layout: k = t + 256r)
    #pragma unroll
    for (int r = 0; r < 16; ++r) {
        const int k = t + NT * r;
        v[r] = make_float2(a[k], b[k]);
    }

    // ---- forward FFT ----
    // stage 0: s=1, n=4096
    dft16<-1>(v);
    twiddle16<-1>(v, t, 1.0f / 4096.0f);
    #pragma unroll
    for (int r = 0; r < 16; ++r) bufA[pad(16 * t + r)] = v[r];
    __syncthreads();
    #pragma unroll
    for (int r = 0; r < 16; ++r) v[r] = bufA[pad(t + NT * r)];

    // stage 1: s=16, n=256
    dft16<-1>(v);
    twiddle16<-1>(v, t >> 4, 1.0f / 256.0f);
    {
        const int q = t & 15, p = t >> 4;
        #pragma unroll
        for (int r = 0; r < 16; ++r) bufB[pad(q + 256 * p + 16 * r)] = v[r];
    }
    __syncthreads();
    #pragma unroll
    for (int r = 0; r < 16; ++r) v[r] = bufB[pad(t + NT * r)];

    // stage 2: s=256 (no twiddle) -> spectrum in regs, natural order k = t + 256r
    dft16<-1>(v);

    // ---- unpack + pointwise multiply ----
    #pragma unroll
    for (int r = 0; r < 16; ++r) bufA[pad(t + NT * r)] = v[r];
    __syncthreads();
    #pragma unroll
    for (int r = 0; r < 16; ++r) {
        const int k = t + NT * r;
        const int nk = (NFFT - k) & (NFFT - 1);
        const float2 Zk = v[r];
        const float2 Zn = bufA[pad(nk)];
        // A = (Zk + conj(Zn))/2 ; B = -i*(Zk - conj(Zn))/2 ; C = A*B
        float2 Ak = make_float2(0.5f * (Zk.x + Zn.x), 0.5f * (Zk.y - Zn.y));
        float2 Bk = make_float2(0.5f * (Zk.y + Zn.y), -0.5f * (Zk.x - Zn.x));
        v[r] = cmul(Ak, Bk);
    }

    // ---- inverse FFT (C already in stage-0 register layout) ----
    dft16<1>(v);
    twiddle16<1>(v, t, 1.0f / 4096.0f);
    #pragma unroll
    for (int r = 0; r < 16; ++r) bufB[pad(16 * t + r)] = v[r];
    __syncthreads();
    #pragma unroll
    for (int r = 0; r < 16; ++r) v[r] = bufB[pad(t + NT * r)];

    dft16<1>(v);
    twiddle16<1>(v, t >> 4, 1.0f / 256.0f);
    {
        const int q = t & 15, p = t >> 4;
        #pragma unroll
        for (int r = 0; r < 16; ++r) bufA[pad(q + 256 * p + 16 * r)] = v[r];
    }
    __syncthreads();
    #pragma unroll
    for (int r = 0; r < 16; ++r) v[r] = bufA[pad(t + NT * r)];

    dft16<1>(v);  // time domain, natural order

    float* o = out + (size_t)row * NFFT;
    const float inv = 1.0f / (float)NFFT;
    #pragma unroll
    for (int r = 0; r < 16; ++r) {
        const int k = t + NT * r;
        o[k] = v[r].x * inv;
    }
}

extern "C" void kernel_launch(void* const* d_in, const int* in_sizes, int n_in,
                              void* d_out, int out_size) {
    const float* a = (const float*)d_in[0];
    const float* b = (const float*)d_in[1];
    float* out = (float*)d_out;

    const int rows = in_sizes[0] / NFFT;  // 8192
    const size_t smem_bytes = 2 * 4352 * sizeof(float2);  // 69632 B

    cudaFuncSetAttribute(circconv16_kernel,
                         cudaFuncAttributeMaxDynamicSharedMemorySize,
                         (int)smem_bytes);
    circconv16_kernel<<<rows, NT, smem_bytes>>>(a, b, out);
}

// round 3
// speedup vs baseline: 2.1162x; 1.1418x over previous
#include <cuda_runtime.h>
#include <cstdint>

// Circular convolution of 8192 rows of length 4096 via packed-real FFT,
// two rows per CTA: Z1 = FFT(a1 + i*a2), Z2 = FFT(b1 + i*b2),
// C = A1*B1 + i*A2*B2, one inverse FFT yields both outputs (Re, Im).
// 3 complex FFTs per 2 rows. Radix-16 Stockham, 3 stages, 256 threads.

#define NFFT 4096
#define NT 256

__device__ __forceinline__ int pad(int i) { return i + (i >> 4); }

__device__ __forceinline__ float2 cadd(float2 a, float2 b) { return make_float2(a.x + b.x, a.y + b.y); }
__device__ __forceinline__ float2 csub(float2 a, float2 b) { return make_float2(a.x - b.x, a.y - b.y); }
__device__ __forceinline__ float2 cmul(float2 a, float2 b) {
    return make_float2(fmaf(a.x, b.x, -a.y * b.y), fmaf(a.x, b.y, a.y * b.x));
}

template <int S>
__device__ __forceinline__ float2 mul_iS(float2 a) {
    return make_float2(-(float)S * a.y, (float)S * a.x);
}

template <int S>
__device__ __forceinline__ void dft8(float2 v[8]) {
    const float r2 = 0.70710678118654752440f;
    float2 u0 = cadd(v[0], v[4]), d0 = csub(v[0], v[4]);
    float2 u1 = cadd(v[1], v[5]), d1 = csub(v[1], v[5]);
    float2 u2 = cadd(v[2], v[6]), d2 = csub(v[2], v[6]);
    float2 u3 = cadd(v[3], v[7]), d3 = csub(v[3], v[7]);
    float2 e1 = make_float2((d1.x - (float)S * d1.y) * r2, (d1.y + (float)S * d1.x) * r2);
    float2 e2 = mul_iS<S>(d2);
    float2 e3 = make_float2((-d3.x - (float)S * d3.y) * r2, (-d3.y + (float)S * d3.x) * r2);

    float2 p0 = cadd(u0, u2), p1 = cadd(u1, u3);
    float2 q0 = csub(u0, u2), q1 = mul_iS<S>(csub(u1, u3));
    v[0] = cadd(p0, p1); v[2] = cadd(q0, q1);
    v[4] = csub(p0, p1); v[6] = csub(q0, q1);

    float2 P0 = cadd(d0, e2), P1 = cadd(e1, e3);
    float2 Q0 = csub(d0, e2), Q1 = mul_iS<S>(csub(e1, e3));
    v[1] = cadd(P0, P1); v[3] = cadd(Q0, Q1);
    v[5] = csub(P0, P1); v[7] = csub(Q0, Q1);
}

template <int S>
__device__ __forceinline__ void dft16(float2 v[16]) {
    float2 e[8], o[8];
    #pragma unroll
    for (int j = 0; j < 8; ++j) { e[j] = v[2 * j]; o[j] = v[2 * j + 1]; }
    dft8<S>(e);
    dft8<S>(o);
    const float COS16[8] = {1.f, 0.9238795325f, 0.7071067812f, 0.3826834324f,
                            0.f, -0.3826834324f, -0.7071067812f, -0.9238795325f};
    const float SIN16[8] = {0.f, 0.3826834324f, 0.7071067812f, 0.9238795325f,
                            1.f, 0.9238795325f, 0.7071067812f, 0.3826834324f};
    #pragma unroll
    for (int k = 0; k < 8; ++k) {
        float2 w = make_float2(COS16[k], (float)S * SIN16[k]);
        float2 t = cmul(o[k], w);
        v[k] = cadd(e[k], t);
        v[k + 8] = csub(e[k], t);
    }
}

template <int S>
__device__ __forceinline__ void twiddle16(float2 v[16], int p, float ninv) {
    float th = (float)S * 6.28318530717958647692f * (float)p * ninv;
    float s1, c1; __sincosf(th, &s1, &c1);
    float s8, c8; __sincosf(8.0f * th, &s8, &c8);
    float2 w1 = make_float2(c1, s1);
    float2 w8 = make_float2(c8, s8);
    v[1] = cmul(v[1], w1);
    float2 wr = w1;
    #pragma unroll
    for (int r = 2; r < 8; ++r) { wr = cmul(wr, w1); v[r] = cmul(v[r], wr); }
    v[8] = cmul(v[8], w8);
    wr = w8;
    #pragma unroll
    for (int r = 9; r < 16; ++r) { wr = cmul(wr, w1); v[r] = cmul(v[r], wr); }
}

// Stage 0 exchange: write 16t+r, read t+256r.
template <int S>
__device__ __forceinline__ void stage0_ex(float2 v[16], float2* buf, int t, bool presync) {
    dft16<S>(v);
    twiddle16<S>(v, t, 1.0f / 4096.0f);
    if (presync) __syncthreads();
    #pragma unroll
    for (int r = 0; r < 16; ++r) buf[pad(16 * t + r)] = v[r];
    __syncthreads();
    #pragma unroll
    for (int r = 0; r < 16; ++r) v[r] = buf[pad(t + NT * r)];
}

// Stage 1 exchange: write q+256p+16r, read t+256r.
template <int S>
__device__ __forceinline__ void stage1_ex(float2 v[16], float2* buf, int t, bool presync) {
    dft16<S>(v);
    twiddle16<S>(v, t >> 4, 1.0f / 256.0f);
    if (presync) __syncthreads();
    const int q = t & 15, p = t >> 4;
    #pragma unroll
    for (int r = 0; r < 16; ++r) buf[pad(q + 256 * p + 16 * r)] = v[r];
    __syncthreads();
    #pragma unroll
    for (int r = 0; r < 16; ++r) v[r] = buf[pad(t + NT * r)];
}

extern __shared__ float2 g_smem[];

__global__ void __launch_bounds__(NT, 2)
circconv2_kernel(const float* __restrict__ A, const float* __restrict__ B,
                 float* __restrict__ out) {
    float2* bufA = g_smem;
    float2* bufB = g_smem + 4352;  // pad(4095)=4350 -> 4352-slot buffers

    const int t = threadIdx.x;
    const size_t row0 = 2 * (size_t)blockIdx.x;
    const float* a1 = A + row0 * NFFT;
    const float* a2 = a1 + NFFT;
    const float* b1 = B + row0 * NFFT;
    const float* b2 = b1 + NFFT;

    float2 v[16];

    // ---- forward FFT of z1 = a1 + i*a2 ----
    #pragma unroll
    for (int r = 0; r < 16; ++r) {
        const int k = t + NT * r;
        v[r] = make_float2(a1[k], a2[k]);
    }
    stage0_ex<-1>(v, bufA, t, false);
    stage1_ex<-1>(v, bufB, t, false);
    dft16<-1>(v);  // Z1 in regs, natural order k = t + 256r

    // Store Z1 spectrum to bufA (all stage-0 reads of bufA completed before
    // the sync inside stage1_ex, so no presync needed).
    #pragma unroll
    for (int r = 0; r < 16; ++r) bufA[pad(t + NT * r)] = v[r];

    // ---- forward FFT of z2 = b1 + i*b2 (uses bufB only) ----
    #pragma unroll
    for (int r = 0; r < 16; ++r) {
        const int k = t + NT * r;
        v[r] = make_float2(b1[k], b2[k]);
    }
    __syncthreads();  // Z1 store visible; bufB stage-1 reads done
    stage0_ex<-1>(v, bufB, t, false);
    stage1_ex<-1>(v, bufB, t, true);  // presync: bufB reads outstanding
    dft16<-1>(v);  // Z2 in regs

    // Store Z2 spectrum to bufB
    __syncthreads();  // bufB reads from stage1_ex done
    #pragma unroll
    for (int r = 0; r < 16; ++r) bufB[pad(t + NT * r)] = v[r];
    __syncthreads();

    // ---- unpack + pointwise multiply ----
    // A1=(Z1k+conj(Z1n))/2, A2=-i(Z1k-conj(Z1n))/2 (spectra of a1,a2)
    // B1=(Z2k+conj(Z2n))/2, B2=-i(Z2k-conj(Z2n))/2 (spectra of b1,b2)
    // C = A1*B1 + i*(A2*B2)
    #pragma unroll
    for (int r = 0; r < 16; ++r) {
        const int k = t + NT * r;
        const int nk = (NFFT - k) & (NFFT - 1);
        const float2 Z2k = v[r];
        const float2 Z1k = bufA[pad(k)];
        const float2 Z1n = bufA[pad(nk)];
        const float2 Z2n = bufB[pad(nk)];
        float2 A1 = make_float2(0.5f * (Z1k.x + Z1n.x), 0.5f * (Z1k.y - Z1n.y));
        float2 A2 = make_float2(0.5f * (Z1k.y + Z1n.y), -0.5f * (Z1k.x - Z1n.x));
        float2 B1 = make_float2(0.5f * (Z2k.x + Z2n.x), 0.5f * (Z2k.y - Z2n.y));
        float2 B2 = make_float2(0.5f * (Z2k.y + Z2n.y), -0.5f * (Z2k.x - Z2n.x));
        float2 C1 = cmul(A1, B1);
        float2 C2 = cmul(A2, B2);
        v[r] = make_float2(C1.x - C2.y, C1.y + C2.x);
    }

    // ---- inverse FFT of C (already in stage-0 register layout) ----
    stage0_ex<1>(v, bufA, t, true);   // presync: multiply reads outstanding
    stage1_ex<1>(v, bufB, t, false);  // bufB reads done before stage0 presync
    dft16<1>(v);  // time domain: Re = conv(a1,b1), Im = conv(a2,b2)

    float* o1 = out + row0 * NFFT;
    float* o2 = o1 + NFFT;
    const float inv = 1.0f / (float)NFFT;
    #pragma unroll
    for (int r = 0; r < 16; ++r) {
        const int k = t + NT * r;
        o1[k] = v[r].x * inv;
        o2[k] = v[r].y * inv;
    }
}

extern "C" void kernel_launch(void* const* d_in, const int* in_sizes, int n_in,
                              void* d_out, int out_size) {
    const float* a = (const float*)d_in[0];
    const float* b = (const float*)d_in[1];
    float* out = (float*)d_out;

    const int rows = in_sizes[0] / NFFT;  // 8192
    const int nblocks = rows / 2;         // 4096
    const size_t smem_bytes = 2 * 4352 * sizeof(float2);  // 69632 B

    cudaFuncSetAttribute(circconv2_kernel,
                         cudaFuncAttributeMaxDynamicSharedMemorySize,
                         (int)smem_bytes);
    circconv2_kernel<<<nblocks, NT, smem_bytes>>>(a, b, out);
}